// round 5
// baseline (speedup 1.0000x reference)
#include <cuda_runtime.h>

#define BATCH 8
#define NPTS 2048
#define DIM 32
#define KNN 16
#define NTOT (BATCH*NPTS)          /* 16384 */
#define YOFF (NTOT*DIM)            /* 524288 */

#define KNN_BLOCKS (NTOT/8)        /* 2048: 8 queries/block */
#define FEAT_BLOCKS (NTOT/32)      /* 512: 32 points/block  */

typedef unsigned long long u64;

// -------- scratch (device globals: no allocation allowed) --------
__device__ float g_xA[NTOT*DIM];
__device__ float g_xB[NTOT*DIM];
__device__ float g_xC[NTOT*DIM];
__device__ int   g_idx[NTOT*KNN];

// -------- packed f32x2 helpers (sm_100a PTX) --------
#define PACK2(d, lo, hi) \
    asm("mov.b64 %0, {%1, %2};" : "=l"(d) : "r"(__float_as_uint(lo)), "r"(__float_as_uint(hi)))
#define UNPACK2(lo, hi, s) do { unsigned _ulo, _uhi; \
    asm("mov.b64 {%0, %1}, %2;" : "=r"(_ulo), "=r"(_uhi) : "l"(s)); \
    lo = __uint_as_float(_ulo); hi = __uint_as_float(_uhi); } while(0)
#define FMA2(acc, a, b) \
    asm("fma.rn.f32x2 %0, %1, %2, %0;" : "+l"(acc) : "l"(a), "l"(b))
#define ADD2(d, a, b) \
    asm("add.rn.f32x2 %0, %1, %2;" : "=l"(d) : "l"(a), "l"(b))
#define SUB2(d, a, b) \
    asm("sub.rn.f32x2 %0, %1, %2;" : "=l"(d) : "l"(a), "l"(b))

// u64 key = (dist_bits << 32) | index, built in one mov.b64
#define MAKEKEY(key, dbits, j) \
    asm("mov.b64 %0, {%1, %2};" : "=l"(key) : "r"(j), "r"(dbits))

// Exact (non-FMA-contracted) squared distance, matching XLA's
// mul/mul/mul + sequential-add lowering of sum((pi-pj)**2, -1).
__device__ __forceinline__ float sqdist_exact(float dx, float dy, float dz) {
    return __fadd_rn(__fadd_rn(__fmul_rn(dx, dx), __fmul_rn(dy, dy)),
                     __fmul_rn(dz, dz));
}

#define INFKEY 0xffffffffffffffffULL

__device__ __forceinline__ void ins3u(u64 k, u64& k0, u64& k1, u64& k2) {
    if (k < k2) {
        if (k < k1) {
            k2 = k1;
            if (k < k0) { k1 = k0; k0 = k; }
            else        { k1 = k; }
        } else k2 = k;
    }
}

__device__ __forceinline__ u64 shfl_xor_u64(u64 v, int m) {
    unsigned lo = (unsigned)v, hi = (unsigned)(v >> 32);
    lo = __shfl_xor_sync(0xffffffffu, lo, m);
    hi = __shfl_xor_sync(0xffffffffu, hi, m);
    return (((u64)hi) << 32) | lo;
}

// ============================================================
// Kernel 1 (fused): blocks [0, KNN_BLOCKS) do 16-NN;
// blocks [KNN_BLOCKS, +FEAT_BLOCKS) do the 3 feature GEMVs + p passthrough.
// ============================================================
__global__ void __launch_bounds__(256, 5) prep_kernel(const float* __restrict__ x,
                                                      const float* __restrict__ p,
                                                      const float* __restrict__ Aw,
                                                      const float* __restrict__ Ab,
                                                      const float* __restrict__ Bw,
                                                      const float* __restrict__ Bb,
                                                      const float* __restrict__ Cw,
                                                      const float* __restrict__ Cb,
                                                      float* __restrict__ out) {
    __shared__ __align__(16) float4 sm4[NPTS];   // 32KB
    int tid = threadIdx.x;
    int warp = tid >> 5, lane = tid & 31;

    if (blockIdx.x < KNN_BLOCKS) {
        // ---------------- KNN branch: warp-per-query, u64 keys ----------------
        int b = blockIdx.x >> 8;                 // 256 blocks per batch
        int qbase = (blockIdx.x & 255) << 3;     // 8 queries per block
        const float* pb = p + b * NPTS * 3;

        for (int u = tid; u < NPTS; u += 256)
            sm4[u] = make_float4(pb[3*u], pb[3*u+1], pb[3*u+2], 0.0f);
        __syncthreads();

        int qi = qbase + warp;
        float4 q4 = sm4[qi];

        u64 k0 = INFKEY, k1 = INFKEY, k2 = INFKEY;
#pragma unroll 4
        for (int t = 0; t < 64; t++) {
            int j = lane + (t << 5);
            float4 c4 = sm4[j];
            float d = sqdist_exact(q4.x - c4.x, q4.y - c4.y, q4.z - c4.z);
            u64 key; MAKEKEY(key, __float_as_uint(d), j);
            ins3u(key, k0, k1, k2);
        }

        int* oi_ptr = g_idx + (b * NPTS + qi) * KNN;
        u64 lp = 0;   // last popped key (pops are strictly increasing)

        for (int r = 0; r < KNN + 1; r++) {
            u64 bk = k0;
#pragma unroll
            for (int off = 16; off > 0; off >>= 1) {
                u64 ok = shfl_xor_u64(bk, off);
                bk = (ok < bk) ? ok : bk;
            }
            if (r > 0 && lane == 0)
                oi_ptr[r - 1] = (int)(unsigned)bk;   // round 0 == self, dropped

            if (k0 == bk) {                          // exactly one winner lane
                lp = k0;
                k0 = k1; k1 = k2; k2 = INFKEY;
                if (k0 == INFKEY) {
                    // refill with 3 smallest keys strictly greater than lp
                    for (int t = 0; t < 64; t++) {
                        int j = lane + (t << 5);
                        float4 c4 = sm4[j];
                        float d = sqdist_exact(q4.x - c4.x, q4.y - c4.y, q4.z - c4.z);
                        u64 key; MAKEKEY(key, __float_as_uint(d), j);
                        if (key > lp) ins3u(key, k0, k1, k2);
                    }
                }
            }
        }
    } else {
        // ---------------- FEAT branch: warp-per-point (4 pts/warp) ----------------
        float* sm = (float*)sm4;
        float* sAw = sm;            // 1024
        float* sBw = sm + 1024;     // 1024
        float* sCw = sm + 2048;     // 1024
        float* sAb = sm + 3072;     // 32
        float* sBb = sm + 3104;     // 32
        float* sCb = sm + 3136;     // 32

        for (int u = tid; u < 1024; u += 256) {
            sAw[u] = Aw[u]; sBw[u] = Bw[u]; sCw[u] = Cw[u];
        }
        if (tid < 32) { sAb[tid] = Ab[tid]; sBb[tid] = Bb[tid]; sCb[tid] = Cb[tid]; }
        __syncthreads();

        int fb = blockIdx.x - KNN_BLOCKS;
        int pt0 = fb * 32 + warp * 4;
#pragma unroll
        for (int q = 0; q < 4; q++) {
            int pt = pt0 + q;
            float xv = x[pt * DIM + lane];
            float a = sAb[lane], bb = sBb[lane], cc = sCb[lane];
#pragma unroll
            for (int d = 0; d < 32; d++) {
                float xd = __shfl_sync(0xffffffffu, xv, d);
                a  = fmaf(xd, sAw[d*32 + lane], a);
                bb = fmaf(xd, sBw[d*32 + lane], bb);
                cc = fmaf(xd, sCw[d*32 + lane], cc);
            }
            g_xA[pt*DIM + lane] = a;
            g_xB[pt*DIM + lane] = bb;
            g_xC[pt*DIM + lane] = cc;
        }
        // p passthrough -> second part of output (96 floats per feat block)
        if (tid < 96) out[YOFF + fb*96 + tid] = p[fb*96 + tid];
    }
}

// ============================================================
// Kernel 2: fused gather + position MLP + value MLP + softmax + y.
// 128 threads = 8 points x 16 neighbors, ONE pair per thread.
// Softmax over k done with 16-lane xor-butterflies (the 16 k's of a
// point live in one half-warp group) -> no h2/val staging in smem.
// ============================================================
__global__ void __launch_bounds__(128, 4) attn_kernel(const float* __restrict__ p,
                                                      const float* __restrict__ pm1w,
                                                      const float* __restrict__ pm1b,
                                                      const float* __restrict__ pm2w,
                                                      const float* __restrict__ pm2b,
                                                      const float* __restrict__ vm1w,
                                                      const float* __restrict__ vm1b,
                                                      const float* __restrict__ vm2w,
                                                      const float* __restrict__ vm2b,
                                                      float* __restrict__ out) {
    __shared__ __align__(16) float s_pm1w[192];
    __shared__ __align__(16) float s_pm1b[64];
    __shared__ __align__(16) float s_pm2w[2048];
    __shared__ __align__(16) float s_pm2b[32];
    __shared__ __align__(16) float s_vm1t[128];   // transposed: [jj][c]
    __shared__ __align__(16) float s_vm1b[4];
    __shared__ __align__(16) float s_vm2w[128];   // [jj][c]
    __shared__ __align__(16) float s_vm2b[32];
    __shared__ __align__(16) float s_xi[8][32];

    int tid = threadIdx.x;
    int gp0 = blockIdx.x << 3;

    // ---- load weights + x_i tile ----
    for (int u = tid; u < 2048; u += 128) s_pm2w[u] = pm2w[u];
    for (int u = tid; u < 192;  u += 128) s_pm1w[u] = pm1w[u];
    if (tid < 64)  s_pm1b[tid] = pm1b[tid];
    if (tid < 32)  { s_pm2b[tid] = pm2b[tid]; s_vm2b[tid] = vm2b[tid]; }
    if (tid < 128) {
        int c = tid >> 2, jj = tid & 3;           // vm1w is [c][jj]
        s_vm1t[jj*32 + c] = vm1w[tid];
        s_vm2w[tid] = vm2w[tid];                  // already [jj][c]
    }
    if (tid < 4) s_vm1b[tid] = vm1b[tid];
    for (int u = tid; u < 256; u += 128)
        s_xi[u >> 5][u & 31] = g_xA[(gp0 << 5) + u];
    __syncthreads();

    int pt = tid >> 4, k = tid & 15;
    int gp = gp0 + pt;
    int b = gp >> 11, ii = gp & 2047;
    int j = g_idx[(gp << 4) + k];

    const float* pb = p + b * NPTS * 3;
    float dx = pb[ii*3 + 0] - pb[j*3 + 0];
    float dy = pb[ii*3 + 1] - pb[j*3 + 1];
    float dz = pb[ii*3 + 2] - pb[j*3 + 2];

    // ---- posi_diff MLP: 3 -> 64 (relu) -> 32, packed accumulators ----
    u64 pd2[16];
#pragma unroll
    for (int i = 0; i < 16; i++)
        pd2[i] = *(const u64*)&s_pm2b[2*i];

#pragma unroll
    for (int ch = 0; ch < 4; ch++) {
        float h1c[16];
#pragma unroll
        for (int m = 0; m < 16; m++) {
            int mg = (ch << 4) + m;
            float v = s_pm1b[mg];
            v = fmaf(dx, s_pm1w[mg],       v);
            v = fmaf(dy, s_pm1w[64 + mg],  v);
            v = fmaf(dz, s_pm1w[128 + mg], v);
            h1c[m] = fmaxf(v, 0.0f);
        }
#pragma unroll
        for (int m = 0; m < 16; m++) {
            int mg = (ch << 4) + m;
            u64 hp; PACK2(hp, h1c[m], h1c[m]);
            const ulonglong2* wr = (const ulonglong2*)&s_pm2w[mg * 32];
#pragma unroll
            for (int i = 0; i < 8; i++) {
                ulonglong2 w = wr[i];                  // LDS.128 = 2 weight pairs
                FMA2(pd2[2*i],     hp, w.x);
                FMA2(pd2[2*i + 1], hp, w.y);
            }
        }
    }

    // ---- gather neighbor rows; h = xi - xB + pd ; vm1 ; pd2 <- val = pd + xC ----
    int row = (b << 11) + j;
    const float4* xb4 = (const float4*)(g_xB + (row << 5));
    const float4* xc4 = (const float4*)(g_xC + (row << 5));

    u64 acc2[4] = {0ull, 0ull, 0ull, 0ull};
#pragma unroll
    for (int q = 0; q < 8; q++) {
        float4 vb = xb4[q];
        float4 vc = xc4[q];
#pragma unroll
        for (int half = 0; half < 2; half++) {
            int pi = 2*q + half;
            int c0 = 4*q + 2*half;
            u64 xbp, xcp;
            if (half == 0) { PACK2(xbp, vb.x, vb.y); PACK2(xcp, vc.x, vc.y); }
            else           { PACK2(xbp, vb.z, vb.w); PACK2(xcp, vc.z, vc.w); }
            u64 xip = *(const u64*)&s_xi[pt][c0];
            u64 t, hpair;
            SUB2(t, xip, xbp);
            ADD2(hpair, t, pd2[pi]);
#pragma unroll
            for (int jj = 0; jj < 4; jj++)
                FMA2(acc2[jj], hpair, *(const u64*)&s_vm1t[jj*32 + c0]);
            u64 valp;
            ADD2(valp, pd2[pi], xcp);
            pd2[pi] = valp;                       // pd2 now holds val
        }
    }

    float hv[4];
#pragma unroll
    for (int jj = 0; jj < 4; jj++) {
        float lo, hi; UNPACK2(lo, hi, acc2[jj]);
        hv[jj] = fmaxf(lo + hi + s_vm1b[jj], 0.0f);
    }
    u64 hvp[4];
#pragma unroll
    for (int jj = 0; jj < 4; jj++) PACK2(hvp[jj], hv[jj], hv[jj]);

    // ---- vm2 + softmax over k, 8 channels per group, all in registers ----
    float y0 = 0.0f, y1 = 0.0f;
#pragma unroll
    for (int g = 0; g < 4; g++) {
        float h2f[8], valf[8];
#pragma unroll
        for (int qq = 0; qq < 4; qq++) {
            int pi = 4*g + qq;
            int c0 = 2*pi;
            u64 h2p = *(const u64*)&s_vm2b[c0];
#pragma unroll
            for (int jj = 0; jj < 4; jj++)
                FMA2(h2p, hvp[jj], *(const u64*)&s_vm2w[jj*32 + c0]);
            UNPACK2(h2f[2*qq], h2f[2*qq+1], h2p);
            UNPACK2(valf[2*qq], valf[2*qq+1], pd2[pi]);
        }
#pragma unroll
        for (int cc = 0; cc < 8; cc++) {
            int c = 8*g + cc;
            float m = h2f[cc];
#pragma unroll
            for (int off = 8; off > 0; off >>= 1)
                m = fmaxf(m, __shfl_xor_sync(0xffffffffu, m, off));
            float e = __expf(h2f[cc] - m);
            float s = e;
            float ya = e * valf[cc];
#pragma unroll
            for (int off = 8; off > 0; off >>= 1) {
                s  += __shfl_xor_sync(0xffffffffu, s,  off);
                ya += __shfl_xor_sync(0xffffffffu, ya, off);
            }
            float yv = ya / s;
            if (c == 2*k)     y0 = yv;
            if (c == 2*k + 1) y1 = yv;
        }
    }

    // lane k writes channels 2k, 2k+1 of its point: 128B contiguous per point
    *(float2*)&out[(gp << 5) + 2*k] = make_float2(y0, y1);
}

// ============================================================
extern "C" void kernel_launch(void* const* d_in, const int* in_sizes, int n_in,
                              void* d_out, int out_size) {
    const float* x = (const float*)d_in[0];
    const float* p = (const float*)d_in[1];

    prep_kernel<<<KNN_BLOCKS + FEAT_BLOCKS, 256>>>(
        x, p,
        (const float*)d_in[2], (const float*)d_in[3],
        (const float*)d_in[4], (const float*)d_in[5],
        (const float*)d_in[6], (const float*)d_in[7],
        (float*)d_out);

    attn_kernel<<<NTOT/8, 128>>>(
        p,
        (const float*)d_in[8],  (const float*)d_in[9],
        (const float*)d_in[10], (const float*)d_in[11],
        (const float*)d_in[12], (const float*)d_in[13],
        (const float*)d_in[14], (const float*)d_in[15],
        (float*)d_out);
}

// round 6
// speedup vs baseline: 1.0510x; 1.0510x over previous
#include <cuda_runtime.h>

#define BATCH 8
#define NPTS 2048
#define DIM 32
#define KNN 16
#define NTOT (BATCH*NPTS)          /* 16384 */
#define YOFF (NTOT*DIM)            /* 524288 */

#define QPB 32                     /* queries per knn block (4 per warp) */
#define KNN_BLOCKS (NTOT/QPB)      /* 512 */
#define FEAT_BLOCKS (NTOT/32)      /* 512: 32 points/block */

typedef unsigned long long u64;

// -------- scratch (device globals: no allocation allowed) --------
__device__ float g_xA[NTOT*DIM];
__device__ float g_xB[NTOT*DIM];
__device__ float g_xC[NTOT*DIM];
__device__ int   g_idx[NTOT*KNN];

// -------- packed f32x2 helpers (sm_100a PTX) --------
#define PACK2(d, lo, hi) \
    asm("mov.b64 %0, {%1, %2};" : "=l"(d) : "r"(__float_as_uint(lo)), "r"(__float_as_uint(hi)))
#define UNPACK2(lo, hi, s) do { unsigned _ulo, _uhi; \
    asm("mov.b64 {%0, %1}, %2;" : "=r"(_ulo), "=r"(_uhi) : "l"(s)); \
    lo = __uint_as_float(_ulo); hi = __uint_as_float(_uhi); } while(0)
#define FMA2(acc, a, b) \
    asm("fma.rn.f32x2 %0, %1, %2, %0;" : "+l"(acc) : "l"(a), "l"(b))
#define ADD2(d, a, b) \
    asm("add.rn.f32x2 %0, %1, %2;" : "=l"(d) : "l"(a), "l"(b))
#define SUB2(d, a, b) \
    asm("sub.rn.f32x2 %0, %1, %2;" : "=l"(d) : "l"(a), "l"(b))

// u64 key = (dist_bits << 32) | index, built in one mov.b64
#define MAKEKEY(key, dbits, j) \
    asm("mov.b64 %0, {%1, %2};" : "=l"(key) : "r"(j), "r"(dbits))

// Exact (non-FMA-contracted) squared distance, matching XLA's
// mul/mul/mul + sequential-add lowering of sum((pi-pj)**2, -1).
__device__ __forceinline__ float sqdist_exact(float dx, float dy, float dz) {
    return __fadd_rn(__fadd_rn(__fmul_rn(dx, dx), __fmul_rn(dy, dy)),
                     __fmul_rn(dz, dz));
}

#define INFKEY 0xffffffffffffffffULL

__device__ __forceinline__ void ins3u(u64 k, u64& k0, u64& k1, u64& k2) {
    if (k < k2) {
        if (k < k1) {
            k2 = k1;
            if (k < k0) { k1 = k0; k0 = k; }
            else        { k1 = k; }
        } else k2 = k;
    }
}

// ============================================================
// Kernel 1 (fused): blocks [0, KNN_BLOCKS) do 16-NN;
// blocks [KNN_BLOCKS, +FEAT_BLOCKS) do the 3 feature GEMVs + p passthrough.
// ============================================================
__global__ void __launch_bounds__(256) prep_kernel(const float* __restrict__ x,
                                                   const float* __restrict__ p,
                                                   const float* __restrict__ Aw,
                                                   const float* __restrict__ Ab,
                                                   const float* __restrict__ Bw,
                                                   const float* __restrict__ Bb,
                                                   const float* __restrict__ Cw,
                                                   const float* __restrict__ Cb,
                                                   float* __restrict__ out) {
    __shared__ __align__(16) float4 sm4[NPTS];   // 32KB
    int tid = threadIdx.x;
    int warp = tid >> 5, lane = tid & 31;

    if (blockIdx.x < KNN_BLOCKS) {
        // ---------------- KNN branch: warp handles 4 queries, tile resident ----
        int b = blockIdx.x >> 6;                 // 64 blocks per batch
        int qbase = (blockIdx.x & 63) << 5;      // 32 queries per block
        const float* pb = p + b * NPTS * 3;

        for (int u = tid; u < NPTS; u += 256)
            sm4[u] = make_float4(pb[3*u], pb[3*u+1], pb[3*u+2], 0.0f);
        __syncthreads();

        for (int qq = 0; qq < 4; qq++) {
            int qi = qbase + warp * 4 + qq;
            float4 q4 = sm4[qi];

            u64 k0 = INFKEY, k1 = INFKEY, k2 = INFKEY;
#pragma unroll 4
            for (int t = 0; t < 64; t++) {
                int j = lane + (t << 5);
                float4 c4 = sm4[j];
                float d = sqdist_exact(q4.x - c4.x, q4.y - c4.y, q4.z - c4.z);
                u64 key; MAKEKEY(key, __float_as_uint(d), j);
                ins3u(key, k0, k1, k2);
            }

            u64 lp = 0;      // last popped key (strictly increasing)
            int myj = 0;     // this lane's buffered output index

            for (int r = 0; r < KNN + 1; r++) {
                // global min key = (min dist bits, min index among that dist)
                unsigned dmin = __reduce_min_sync(0xffffffffu, (unsigned)(k0 >> 32));
                unsigned jc = ((unsigned)(k0 >> 32) == dmin) ? (unsigned)k0 : 0xffffffffu;
                unsigned jmin = __reduce_min_sync(0xffffffffu, jc);
                u64 bk; MAKEKEY(bk, dmin, jmin);

                if (lane == r - 1) myj = (int)jmin;  // round 0 == self, dropped

                if (k0 == bk) {                      // exactly one winner lane
                    lp = k0;
                    k0 = k1; k1 = k2; k2 = INFKEY;
                    if (k0 == INFKEY) {
                        // refill with 3 smallest keys strictly greater than lp
                        for (int t = 0; t < 64; t++) {
                            int j = lane + (t << 5);
                            float4 c4 = sm4[j];
                            float d = sqdist_exact(q4.x - c4.x, q4.y - c4.y, q4.z - c4.z);
                            u64 key; MAKEKEY(key, __float_as_uint(d), j);
                            if (key > lp) ins3u(key, k0, k1, k2);
                        }
                    }
                }
            }
            if (lane < KNN)
                g_idx[(b * NPTS + qi) * KNN + lane] = myj;   // coalesced
        }
    } else {
        // ---------------- FEAT branch: warp-per-point (4 pts/warp) ----------------
        float* sm = (float*)sm4;
        float* sAw = sm;            // 1024
        float* sBw = sm + 1024;     // 1024
        float* sCw = sm + 2048;     // 1024
        float* sAb = sm + 3072;     // 32
        float* sBb = sm + 3104;     // 32
        float* sCb = sm + 3136;     // 32

        for (int u = tid; u < 1024; u += 256) {
            sAw[u] = Aw[u]; sBw[u] = Bw[u]; sCw[u] = Cw[u];
        }
        if (tid < 32) { sAb[tid] = Ab[tid]; sBb[tid] = Bb[tid]; sCb[tid] = Cb[tid]; }
        __syncthreads();

        int fb = blockIdx.x - KNN_BLOCKS;
        int pt0 = fb * 32 + warp * 4;
#pragma unroll
        for (int q = 0; q < 4; q++) {
            int pt = pt0 + q;
            float xv = x[pt * DIM + lane];
            float a = sAb[lane], bb = sBb[lane], cc = sCb[lane];
#pragma unroll
            for (int d = 0; d < 32; d++) {
                float xd = __shfl_sync(0xffffffffu, xv, d);
                a  = fmaf(xd, sAw[d*32 + lane], a);
                bb = fmaf(xd, sBw[d*32 + lane], bb);
                cc = fmaf(xd, sCw[d*32 + lane], cc);
            }
            g_xA[pt*DIM + lane] = a;
            g_xB[pt*DIM + lane] = bb;
            g_xC[pt*DIM + lane] = cc;
        }
        // p passthrough -> second part of output (96 floats per feat block)
        if (tid < 96) out[YOFF + fb*96 + tid] = p[fb*96 + tid];
    }
}

// ============================================================
// Kernel 2: fused gather + position MLP + value MLP + softmax + y.
// 128 threads = 8 points x 16 neighbors, one pair per thread (R3
// structure: smem-staged h2/val, two-pass softmax). f32x2 math.
// ============================================================
__global__ void __launch_bounds__(128, 4) attn_kernel(const float* __restrict__ p,
                                                      const float* __restrict__ pm1w,
                                                      const float* __restrict__ pm1b,
                                                      const float* __restrict__ pm2w,
                                                      const float* __restrict__ pm2b,
                                                      const float* __restrict__ vm1w,
                                                      const float* __restrict__ vm1b,
                                                      const float* __restrict__ vm2w,
                                                      const float* __restrict__ vm2b,
                                                      float* __restrict__ out) {
    __shared__ __align__(16) float s_pm1w[192];
    __shared__ __align__(16) float s_pm1b[64];
    __shared__ __align__(16) float s_pm2w[2048];
    __shared__ __align__(16) float s_pm2b[32];
    __shared__ __align__(16) float s_vm1t[128];   // transposed: [jj][c]
    __shared__ __align__(16) float s_vm1b[4];
    __shared__ __align__(16) float s_vm2w[128];   // [jj][c]
    __shared__ __align__(16) float s_vm2b[32];
    __shared__ __align__(16) float s_xi[8][32];
    __shared__ __align__(16) float s_h2[8][16][34];
    __shared__ __align__(16) float s_val[8][16][34];

    int tid = threadIdx.x;
    int gp0 = blockIdx.x << 3;

    // ---- load weights + x_i tile ----
    for (int u = tid; u < 2048; u += 128) s_pm2w[u] = pm2w[u];
    for (int u = tid; u < 192;  u += 128) s_pm1w[u] = pm1w[u];
    if (tid < 64)  s_pm1b[tid] = pm1b[tid];
    if (tid < 32)  { s_pm2b[tid] = pm2b[tid]; s_vm2b[tid] = vm2b[tid]; }
    if (tid < 128) {
        int c = tid >> 2, jj = tid & 3;           // vm1w is [c][jj]
        s_vm1t[jj*32 + c] = vm1w[tid];
        s_vm2w[tid] = vm2w[tid];                  // already [jj][c]
    }
    if (tid < 4) s_vm1b[tid] = vm1b[tid];
    for (int u = tid; u < 256; u += 128)
        s_xi[u >> 5][u & 31] = g_xA[(gp0 << 5) + u];
    __syncthreads();

    int pt = tid >> 4, k = tid & 15;
    int gp = gp0 + pt;
    int b = gp >> 11, ii = gp & 2047;
    int j = g_idx[(gp << 4) + k];

    const float* pb = p + b * NPTS * 3;
    float dx = pb[ii*3 + 0] - pb[j*3 + 0];
    float dy = pb[ii*3 + 1] - pb[j*3 + 1];
    float dz = pb[ii*3 + 2] - pb[j*3 + 2];

    // ---- posi_diff MLP: 3 -> 64 (relu) -> 32, packed accumulators ----
    u64 pd2[16];
#pragma unroll
    for (int i = 0; i < 16; i++)
        pd2[i] = *(const u64*)&s_pm2b[2*i];

#pragma unroll
    for (int ch = 0; ch < 4; ch++) {
        float h1c[16];
#pragma unroll
        for (int m = 0; m < 16; m++) {
            int mg = (ch << 4) + m;
            float v = s_pm1b[mg];
            v = fmaf(dx, s_pm1w[mg],       v);
            v = fmaf(dy, s_pm1w[64 + mg],  v);
            v = fmaf(dz, s_pm1w[128 + mg], v);
            h1c[m] = fmaxf(v, 0.0f);
        }
#pragma unroll
        for (int m = 0; m < 16; m++) {
            int mg = (ch << 4) + m;
            u64 hp; PACK2(hp, h1c[m], h1c[m]);
            const ulonglong2* wr = (const ulonglong2*)&s_pm2w[mg * 32];
#pragma unroll
            for (int i = 0; i < 8; i++) {
                ulonglong2 w = wr[i];                  // LDS.128 = 2 weight pairs
                FMA2(pd2[2*i],     hp, w.x);
                FMA2(pd2[2*i + 1], hp, w.y);
            }
        }
    }

    // ---- gather neighbor rows; h = xi - xB + pd ; vm1 ; val -> smem ----
    int row = (b << 11) + j;
    const float4* xb4 = (const float4*)(g_xB + (row << 5));
    const float4* xc4 = (const float4*)(g_xC + (row << 5));

    u64 acc2[4] = {0ull, 0ull, 0ull, 0ull};
#pragma unroll
    for (int q = 0; q < 8; q++) {
        float4 vb = xb4[q];
        float4 vc = xc4[q];
#pragma unroll
        for (int half = 0; half < 2; half++) {
            int pi = 2*q + half;
            int c0 = 4*q + 2*half;
            u64 xbp, xcp;
            if (half == 0) { PACK2(xbp, vb.x, vb.y); PACK2(xcp, vc.x, vc.y); }
            else           { PACK2(xbp, vb.z, vb.w); PACK2(xcp, vc.z, vc.w); }
            u64 xip = *(const u64*)&s_xi[pt][c0];
            u64 t, hpair;
            SUB2(t, xip, xbp);
            ADD2(hpair, t, pd2[pi]);
#pragma unroll
            for (int jj = 0; jj < 4; jj++)
                FMA2(acc2[jj], hpair, *(const u64*)&s_vm1t[jj*32 + c0]);
            u64 valp;
            ADD2(valp, pd2[pi], xcp);
            *(u64*)&s_val[pt][k][c0] = valp;
        }
    }

    float hv[4];
#pragma unroll
    for (int jj = 0; jj < 4; jj++) {
        float lo, hi; UNPACK2(lo, hi, acc2[jj]);
        hv[jj] = fmaxf(lo + hi + s_vm1b[jj], 0.0f);
    }

    // ---- vm2: h2 = vm2b + hv @ vm2w  (packed over c-pairs) ----
    u64 hvp[4];
#pragma unroll
    for (int jj = 0; jj < 4; jj++) PACK2(hvp[jj], hv[jj], hv[jj]);
#pragma unroll
    for (int pi = 0; pi < 16; pi++) {
        int c0 = 2*pi;
        u64 h2p = *(const u64*)&s_vm2b[c0];
#pragma unroll
        for (int jj = 0; jj < 4; jj++)
            FMA2(h2p, hvp[jj], *(const u64*)&s_vm2w[jj*32 + c0]);
        *(u64*)&s_h2[pt][k][c0] = h2p;
    }
    __syncthreads();

    // ---- softmax over k per (pt, c) + weighted sum ----
    for (int task = tid; task < 256; task += 128) {
        int tp = task >> 5, c = task & 31;
        float m = s_h2[tp][0][c];
#pragma unroll
        for (int kk = 1; kk < 16; kk++) m = fmaxf(m, s_h2[tp][kk][c]);
        float s = 0.0f, acc = 0.0f;
#pragma unroll
        for (int kk = 0; kk < 16; kk++) {
            float e = __expf(s_h2[tp][kk][c] - m);
            s += e;
            acc = fmaf(e, s_val[tp][kk][c], acc);
        }
        out[((gp0 + tp) << 5) + c] = acc / s;
    }
}

// ============================================================
extern "C" void kernel_launch(void* const* d_in, const int* in_sizes, int n_in,
                              void* d_out, int out_size) {
    const float* x = (const float*)d_in[0];
    const float* p = (const float*)d_in[1];

    prep_kernel<<<KNN_BLOCKS + FEAT_BLOCKS, 256>>>(
        x, p,
        (const float*)d_in[2], (const float*)d_in[3],
        (const float*)d_in[4], (const float*)d_in[5],
        (const float*)d_in[6], (const float*)d_in[7],
        (float*)d_out);

    attn_kernel<<<NTOT/8, 128>>>(
        p,
        (const float*)d_in[8],  (const float*)d_in[9],
        (const float*)d_in[10], (const float*)d_in[11],
        (const float*)d_in[12], (const float*)d_in[13],
        (const float*)d_in[14], (const float*)d_in[15],
        (float*)d_out);
}

// round 7
// speedup vs baseline: 1.2331x; 1.1733x over previous
#include <cuda_runtime.h>

#define BATCH 8
#define NPTS 2048
#define DIM 32
#define KNN 16
#define NTOT (BATCH*NPTS)          /* 16384 */
#define YOFF (NTOT*DIM)            /* 524288 */

#define KNN_BLOCKS (NTOT/8)        /* 2048: 8 queries/block, warp per query */
#define FEAT_BLOCKS (NTOT/32)      /* 512: 32 points/block */

typedef unsigned long long u64;

// -------- scratch (device globals: no allocation allowed) --------
__device__ float g_xA[NTOT*DIM];
__device__ float g_xB[NTOT*DIM];
__device__ float g_xC[NTOT*DIM];
__device__ int   g_idx[NTOT*KNN];

// -------- packed f32x2 helpers (sm_100a PTX) --------
#define PACK2(d, lo, hi) \
    asm("mov.b64 %0, {%1, %2};" : "=l"(d) : "r"(__float_as_uint(lo)), "r"(__float_as_uint(hi)))
#define UNPACK2(lo, hi, s) do { unsigned _ulo, _uhi; \
    asm("mov.b64 {%0, %1}, %2;" : "=r"(_ulo), "=r"(_uhi) : "l"(s)); \
    lo = __uint_as_float(_ulo); hi = __uint_as_float(_uhi); } while(0)
#define FMA2(acc, a, b) \
    asm("fma.rn.f32x2 %0, %1, %2, %0;" : "+l"(acc) : "l"(a), "l"(b))
#define ADD2(d, a, b) \
    asm("add.rn.f32x2 %0, %1, %2;" : "=l"(d) : "l"(a), "l"(b))
#define SUB2(d, a, b) \
    asm("sub.rn.f32x2 %0, %1, %2;" : "=l"(d) : "l"(a), "l"(b))

// u64 key = (dist_bits << 32) | index, built in one mov.b64
#define MAKEKEY(key, dbits, j) \
    asm("mov.b64 %0, {%1, %2};" : "=l"(key) : "r"(j), "r"(dbits))

// Exact (non-FMA-contracted) squared distance, matching XLA's
// mul/mul/mul + sequential-add lowering of sum((pi-pj)**2, -1).
__device__ __forceinline__ float sqdist_exact(float dx, float dy, float dz) {
    return __fadd_rn(__fadd_rn(__fmul_rn(dx, dx), __fmul_rn(dy, dy)),
                     __fmul_rn(dz, dz));
}

#define INFKEY 0xffffffffffffffffULL

__device__ __forceinline__ void ins3u(u64 k, u64& k0, u64& k1, u64& k2) {
    if (k < k2) {
        if (k < k1) {
            k2 = k1;
            if (k < k0) { k1 = k0; k0 = k; }
            else        { k1 = k; }
        } else k2 = k;
    }
}

// ============================================================
// Kernel 1 (fused): blocks [0, KNN_BLOCKS) do 16-NN (warp/query);
// blocks [KNN_BLOCKS, +FEAT_BLOCKS) do the 3 feature GEMVs + p passthrough.
// ============================================================
__global__ void __launch_bounds__(256, 5) prep_kernel(const float* __restrict__ x,
                                                      const float* __restrict__ p,
                                                      const float* __restrict__ Aw,
                                                      const float* __restrict__ Ab,
                                                      const float* __restrict__ Bw,
                                                      const float* __restrict__ Bb,
                                                      const float* __restrict__ Cw,
                                                      const float* __restrict__ Cb,
                                                      float* __restrict__ out) {
    __shared__ __align__(16) float4 sm4[NPTS];   // 32KB
    int tid = threadIdx.x;
    int warp = tid >> 5, lane = tid & 31;

    if (blockIdx.x < KNN_BLOCKS) {
        // ---------------- KNN branch: warp-per-query, redux extraction -------
        int b = blockIdx.x >> 8;                 // 256 blocks per batch
        int qbase = (blockIdx.x & 255) << 3;     // 8 queries per block
        const float* pb = p + b * NPTS * 3;

        for (int u = tid; u < NPTS; u += 256)
            sm4[u] = make_float4(pb[3*u], pb[3*u+1], pb[3*u+2], 0.0f);
        __syncthreads();

        int qi = qbase + warp;
        float4 q4 = sm4[qi];

        u64 k0 = INFKEY, k1 = INFKEY, k2 = INFKEY;
#pragma unroll 4
        for (int t = 0; t < 64; t++) {
            int j = lane + (t << 5);
            float4 c4 = sm4[j];
            float d = sqdist_exact(q4.x - c4.x, q4.y - c4.y, q4.z - c4.z);
            u64 key; MAKEKEY(key, __float_as_uint(d), j);
            ins3u(key, k0, k1, k2);
        }

        u64 lp = 0;      // last popped key (strictly increasing)
        int myj = 0;     // this lane's buffered output index

        for (int r = 0; r < KNN + 1; r++) {
            // global min key = (min dist bits, then min index among that dist)
            unsigned dmin = __reduce_min_sync(0xffffffffu, (unsigned)(k0 >> 32));
            unsigned jc = ((unsigned)(k0 >> 32) == dmin) ? (unsigned)k0 : 0xffffffffu;
            unsigned jmin = __reduce_min_sync(0xffffffffu, jc);
            u64 bk; MAKEKEY(bk, dmin, jmin);

            if (lane == r - 1) myj = (int)jmin;  // round 0 == self, dropped

            if (k0 == bk) {                      // exactly one winner lane
                lp = k0;
                k0 = k1; k1 = k2; k2 = INFKEY;
                if (k0 == INFKEY) {
                    // refill with 3 smallest keys strictly greater than lp
                    for (int t = 0; t < 64; t++) {
                        int j = lane + (t << 5);
                        float4 c4 = sm4[j];
                        float d = sqdist_exact(q4.x - c4.x, q4.y - c4.y, q4.z - c4.z);
                        u64 key; MAKEKEY(key, __float_as_uint(d), j);
                        if (key > lp) ins3u(key, k0, k1, k2);
                    }
                }
            }
        }
        if (lane < KNN)
            g_idx[(b * NPTS + qi) * KNN + lane] = myj;   // coalesced
    } else {
        // ---------------- FEAT branch: warp-per-point (4 pts/warp) ----------------
        float* sm = (float*)sm4;
        float* sAw = sm;            // 1024
        float* sBw = sm + 1024;     // 1024
        float* sCw = sm + 2048;     // 1024
        float* sAb = sm + 3072;     // 32
        float* sBb = sm + 3104;     // 32
        float* sCb = sm + 3136;     // 32

        for (int u = tid; u < 1024; u += 256) {
            sAw[u] = Aw[u]; sBw[u] = Bw[u]; sCw[u] = Cw[u];
        }
        if (tid < 32) { sAb[tid] = Ab[tid]; sBb[tid] = Bb[tid]; sCb[tid] = Cb[tid]; }
        __syncthreads();

        int fb = blockIdx.x - KNN_BLOCKS;
        int pt0 = fb * 32 + warp * 4;
#pragma unroll
        for (int q = 0; q < 4; q++) {
            int pt = pt0 + q;
            float xv = x[pt * DIM + lane];
            float a = sAb[lane], bb = sBb[lane], cc = sCb[lane];
#pragma unroll
            for (int d = 0; d < 32; d++) {
                float xd = __shfl_sync(0xffffffffu, xv, d);
                a  = fmaf(xd, sAw[d*32 + lane], a);
                bb = fmaf(xd, sBw[d*32 + lane], bb);
                cc = fmaf(xd, sCw[d*32 + lane], cc);
            }
            g_xA[pt*DIM + lane] = a;
            g_xB[pt*DIM + lane] = bb;
            g_xC[pt*DIM + lane] = cc;
        }
        // p passthrough -> second part of output (96 floats per feat block)
        if (tid < 96) out[YOFF + fb*96 + tid] = p[fb*96 + tid];
    }
}

// ============================================================
// Kernel 2: fused gather + position MLP + value MLP + softmax + y.
// 128 threads = 8 points x 16 neighbors, one pair per thread.
// smem-staged h2/val, two-pass softmax. Pad-33 rows (44.9KB total)
// -> 5 blocks/SM. Stores to h2/val use STS.32; banks (33k+c)%32 =
// (k+c)%32, conflict-free.
// ============================================================
__global__ void __launch_bounds__(128, 5) attn_kernel(const float* __restrict__ p,
                                                      const float* __restrict__ pm1w,
                                                      const float* __restrict__ pm1b,
                                                      const float* __restrict__ pm2w,
                                                      const float* __restrict__ pm2b,
                                                      const float* __restrict__ vm1w,
                                                      const float* __restrict__ vm1b,
                                                      const float* __restrict__ vm2w,
                                                      const float* __restrict__ vm2b,
                                                      float* __restrict__ out) {
    __shared__ __align__(16) float s_pm1w[192];
    __shared__ __align__(16) float s_pm1b[64];
    __shared__ __align__(16) float s_pm2w[2048];
    __shared__ __align__(16) float s_pm2b[32];
    __shared__ __align__(16) float s_vm1t[128];   // transposed: [jj][c]
    __shared__ __align__(16) float s_vm1b[4];
    __shared__ __align__(16) float s_vm2w[128];   // [jj][c]
    __shared__ __align__(16) float s_vm2b[32];
    __shared__ __align__(16) float s_xi[8][32];
    __shared__ __align__(16) float s_h2[8][16][33];
    __shared__ __align__(16) float s_val[8][16][33];

    int tid = threadIdx.x;
    int gp0 = blockIdx.x << 3;

    // ---- load weights + x_i tile ----
    for (int u = tid; u < 2048; u += 128) s_pm2w[u] = pm2w[u];
    for (int u = tid; u < 192;  u += 128) s_pm1w[u] = pm1w[u];
    if (tid < 64)  s_pm1b[tid] = pm1b[tid];
    if (tid < 32)  { s_pm2b[tid] = pm2b[tid]; s_vm2b[tid] = vm2b[tid]; }
    if (tid < 128) {
        int c = tid >> 2, jj = tid & 3;           // vm1w is [c][jj]
        s_vm1t[jj*32 + c] = vm1w[tid];
        s_vm2w[tid] = vm2w[tid];                  // already [jj][c]
    }
    if (tid < 4) s_vm1b[tid] = vm1b[tid];
    for (int u = tid; u < 256; u += 128)
        s_xi[u >> 5][u & 31] = g_xA[(gp0 << 5) + u];
    __syncthreads();

    int pt = tid >> 4, k = tid & 15;
    int gp = gp0 + pt;
    int b = gp >> 11, ii = gp & 2047;
    int j = g_idx[(gp << 4) + k];

    const float* pb = p + b * NPTS * 3;
    float dx = pb[ii*3 + 0] - pb[j*3 + 0];
    float dy = pb[ii*3 + 1] - pb[j*3 + 1];
    float dz = pb[ii*3 + 2] - pb[j*3 + 2];

    // ---- posi_diff MLP: 3 -> 64 (relu) -> 32, packed accumulators ----
    u64 pd2[16];
#pragma unroll
    for (int i = 0; i < 16; i++)
        pd2[i] = *(const u64*)&s_pm2b[2*i];

#pragma unroll
    for (int ch = 0; ch < 4; ch++) {
        float h1c[16];
#pragma unroll
        for (int m = 0; m < 16; m++) {
            int mg = (ch << 4) + m;
            float v = s_pm1b[mg];
            v = fmaf(dx, s_pm1w[mg],       v);
            v = fmaf(dy, s_pm1w[64 + mg],  v);
            v = fmaf(dz, s_pm1w[128 + mg], v);
            h1c[m] = fmaxf(v, 0.0f);
        }
#pragma unroll
        for (int m = 0; m < 16; m++) {
            int mg = (ch << 4) + m;
            u64 hp; PACK2(hp, h1c[m], h1c[m]);
            const ulonglong2* wr = (const ulonglong2*)&s_pm2w[mg * 32];
#pragma unroll
            for (int i = 0; i < 8; i++) {
                ulonglong2 w = wr[i];                  // LDS.128 = 2 weight pairs
                FMA2(pd2[2*i],     hp, w.x);
                FMA2(pd2[2*i + 1], hp, w.y);
            }
        }
    }

    // ---- gather neighbor rows; h = xi - xB + pd ; vm1 ; val -> smem ----
    int row = (b << 11) + j;
    const float4* xb4 = (const float4*)(g_xB + (row << 5));
    const float4* xc4 = (const float4*)(g_xC + (row << 5));

    u64 acc2[4] = {0ull, 0ull, 0ull, 0ull};
#pragma unroll
    for (int q = 0; q < 8; q++) {
        float4 vb = xb4[q];
        float4 vc = xc4[q];
#pragma unroll
        for (int half = 0; half < 2; half++) {
            int pi = 2*q + half;
            int c0 = 4*q + 2*half;
            u64 xbp, xcp;
            if (half == 0) { PACK2(xbp, vb.x, vb.y); PACK2(xcp, vc.x, vc.y); }
            else           { PACK2(xbp, vb.z, vb.w); PACK2(xcp, vc.z, vc.w); }
            u64 xip = *(const u64*)&s_xi[pt][c0];
            u64 t, hpair;
            SUB2(t, xip, xbp);
            ADD2(hpair, t, pd2[pi]);
#pragma unroll
            for (int jj = 0; jj < 4; jj++)
                FMA2(acc2[jj], hpair, *(const u64*)&s_vm1t[jj*32 + c0]);
            u64 valp;
            ADD2(valp, pd2[pi], xcp);
            float vlo, vhi; UNPACK2(vlo, vhi, valp);
            s_val[pt][k][c0]     = vlo;
            s_val[pt][k][c0 + 1] = vhi;
        }
    }

    float hv[4];
#pragma unroll
    for (int jj = 0; jj < 4; jj++) {
        float lo, hi; UNPACK2(lo, hi, acc2[jj]);
        hv[jj] = fmaxf(lo + hi + s_vm1b[jj], 0.0f);
    }

    // ---- vm2: h2 = vm2b + hv @ vm2w  (packed over c-pairs) ----
    u64 hvp[4];
#pragma unroll
    for (int jj = 0; jj < 4; jj++) PACK2(hvp[jj], hv[jj], hv[jj]);
#pragma unroll
    for (int pi = 0; pi < 16; pi++) {
        int c0 = 2*pi;
        u64 h2p = *(const u64*)&s_vm2b[c0];
#pragma unroll
        for (int jj = 0; jj < 4; jj++)
            FMA2(h2p, hvp[jj], *(const u64*)&s_vm2w[jj*32 + c0]);
        float hlo, hhi; UNPACK2(hlo, hhi, h2p);
        s_h2[pt][k][c0]     = hlo;
        s_h2[pt][k][c0 + 1] = hhi;
    }
    __syncthreads();

    // ---- softmax over k per (pt, c) + weighted sum ----
    for (int task = tid; task < 256; task += 128) {
        int tp = task >> 5, c = task & 31;
        float m = s_h2[tp][0][c];
#pragma unroll
        for (int kk = 1; kk < 16; kk++) m = fmaxf(m, s_h2[tp][kk][c]);
        float s = 0.0f, acc = 0.0f;
#pragma unroll
        for (int kk = 0; kk < 16; kk++) {
            float e = __expf(s_h2[tp][kk][c] - m);
            s += e;
            acc = fmaf(e, s_val[tp][kk][c], acc);
        }
        out[((gp0 + tp) << 5) + c] = acc / s;
    }
}

// ============================================================
extern "C" void kernel_launch(void* const* d_in, const int* in_sizes, int n_in,
                              void* d_out, int out_size) {
    const float* x = (const float*)d_in[0];
    const float* p = (const float*)d_in[1];

    prep_kernel<<<KNN_BLOCKS + FEAT_BLOCKS, 256>>>(
        x, p,
        (const float*)d_in[2], (const float*)d_in[3],
        (const float*)d_in[4], (const float*)d_in[5],
        (const float*)d_in[6], (const float*)d_in[7],
        (float*)d_out);

    attn_kernel<<<NTOT/8, 128>>>(
        p,
        (const float*)d_in[8],  (const float*)d_in[9],
        (const float*)d_in[10], (const float*)d_in[11],
        (const float*)d_in[12], (const float*)d_in[13],
        (const float*)d_in[14], (const float*)d_in[15],
        (float*)d_out);
}